// round 1
// baseline (speedup 1.0000x reference)
#include <cuda_runtime.h>

#define NUM_NET 2
#define V 100000
#define D 128
#define B 4096
#define K 5
#define NS 10

__device__ double g_acc;

__global__ void zero_acc_kernel() { g_acc = 0.0; }

__device__ __forceinline__ float logsig(float x) {
    // numerically stable log(sigmoid(x)) = min(x,0) - log1p(exp(-|x|))
    return fminf(x, 0.0f) - log1pf(expf(-fabsf(x)));
}

__device__ __forceinline__ float warp_sum(float s) {
    #pragma unroll
    for (int off = 16; off; off >>= 1)
        s += __shfl_xor_sync(0xffffffffu, s, off);
    return s;
}

// Sum of logsig(sign * (ctx_row . node_emb)) over M gathered context rows.
// Warp-cooperative: each lane holds 4 of the 128 dims (float4).
__device__ __forceinline__ float rows_sum(const float* __restrict__ tab,
                                          const int* __restrict__ idx,
                                          int M, bool negate,
                                          float4 ne, int lane) {
    float a = 0.0f;
    int id0 = __ldg(idx);
    float4 c = __ldg(reinterpret_cast<const float4*>(tab + (size_t)id0 * D) + lane);
    for (int m = 0; m < M; m++) {
        float4 cur = c;
        if (m + 1 < M) {
            int idn = __ldg(idx + m + 1);
            c = __ldg(reinterpret_cast<const float4*>(tab + (size_t)idn * D) + lane);
        }
        float s = fmaf(ne.x, cur.x, fmaf(ne.y, cur.y, fmaf(ne.z, cur.z, ne.w * cur.w)));
        s = warp_sum(s);
        a += logsig(negate ? -s : s);
    }
    return a;
}

__global__ void __launch_bounds__(256, 4)
loss_kernel(const float* __restrict__ node_tables,
            const float* __restrict__ neigh_tables,
            const int* __restrict__ nodes_idx,
            const int* __restrict__ neigh_idx,
            const int* __restrict__ role_idx,
            const int* __restrict__ neg_main,
            const int* __restrict__ neg_node,
            const int* __restrict__ neg_cross,
            const int* __restrict__ neg_role) {
    const int lane = threadIdx.x & 31;
    const int wid  = threadIdx.x >> 5;
    const int gw   = blockIdx.x * (blockDim.x >> 5) + wid;

    __shared__ float sacc[8];
    float acc = 0.0f;

    if (gw < NUM_NET * B) {
        const int i = gw / B;
        const int b = gw % B;
        const int j = 1 - i;
        const size_t VD = (size_t)V * D;

        const float* nt_i = node_tables  + (size_t)i * VD;
        const float* nt_j = node_tables  + (size_t)j * VD;
        const float* gt_i = neigh_tables + (size_t)i * VD;
        const float* gt_j = neigh_tables + (size_t)j * VD;

        // node embedding for (i, b): 4 floats per lane
        const int nid = __ldg(nodes_idx + i * B + b);
        const float4 ne = __ldg(reinterpret_cast<const float4*>(nt_i + (size_t)nid * D) + lane);

        // Folded coefficients: total = -(1/10) * sum_t w_t * [ pos_sum/(B*Mpos) + neg_sum/B ]
        const float CB = 1.0f / (10.0f * (float)B);
        const float W1 = 1.0f, WH = 0.1f;

        // term 1: main SGNS on view i
        acc += rows_sum(gt_i, neigh_idx + (i * B + b) * K, K, false, ne, lane) * (-W1 * CB / (float)K);
        acc += rows_sum(gt_i, neg_main + (size_t)(i * B + b) * (K * NS), K * NS, true, ne, lane) * (-W1 * CB);

        // term 2: cross-view node alignment (j != i)
        acc += rows_sum(nt_j, nodes_idx + i * B + b, 1, false, ne, lane) * (-WH * CB);
        acc += rows_sum(nt_j, neg_node + (size_t)((i * NUM_NET + j) * B + b) * NS, NS, true, ne, lane) * (-WH * CB);

        // term 3: cross-view neighbor loss (j != i)
        acc += rows_sum(gt_j, neigh_idx + (i * B + b) * K, K, false, ne, lane) * (-WH * CB / (float)K);
        acc += rows_sum(gt_j, neg_cross + (size_t)((i * NUM_NET + j) * B + b) * (K * NS), K * NS, true, ne, lane) * (-WH * CB);

        // terms 4,5: role-based loss for all j2 in {0,1}
        #pragma unroll
        for (int j2 = 0; j2 < NUM_NET; j2++) {
            const float* nt = node_tables + (size_t)j2 * VD;
            acc += rows_sum(nt, role_idx + (i * NUM_NET + j2) * B + b, 1, false, ne, lane) * (-WH * CB);
            acc += rows_sum(nt, neg_role + (size_t)((i * NUM_NET + j2) * B + b) * NS, NS, true, ne, lane) * (-WH * CB);
        }
    }

    // every lane of a warp holds an identical acc; lane 0 publishes it
    if (lane == 0) sacc[wid] = acc;
    __syncthreads();
    if (threadIdx.x == 0) {
        float t = 0.0f;
        const int nw = blockDim.x >> 5;
        for (int w = 0; w < nw; w++) t += sacc[w];
        atomicAdd(&g_acc, (double)t);
    }
}

__global__ void finalize_kernel(float* __restrict__ out) {
    out[0] = (float)g_acc;
}

extern "C" void kernel_launch(void* const* d_in, const int* in_sizes, int n_in,
                              void* d_out, int out_size) {
    const float* node_tables  = (const float*)d_in[0];
    const float* neigh_tables = (const float*)d_in[1];
    const int*   nodes_idx    = (const int*)d_in[2];
    const int*   neigh_idx    = (const int*)d_in[3];
    const int*   role_idx     = (const int*)d_in[4];
    const int*   neg_main     = (const int*)d_in[5];
    const int*   neg_node     = (const int*)d_in[6];
    const int*   neg_cross    = (const int*)d_in[7];
    const int*   neg_role     = (const int*)d_in[8];

    (void)in_sizes; (void)n_in; (void)out_size;

    zero_acc_kernel<<<1, 1>>>();

    const int warps_total = NUM_NET * B;       // 8192 warps
    const int threads = 256;                   // 8 warps/block
    const int blocks = (warps_total * 32 + threads - 1) / threads;  // 1024
    loss_kernel<<<blocks, threads>>>(node_tables, neigh_tables, nodes_idx,
                                     neigh_idx, role_idx, neg_main,
                                     neg_node, neg_cross, neg_role);

    finalize_kernel<<<1, 1>>>((float*)d_out);
}

// round 2
// speedup vs baseline: 1.3233x; 1.3233x over previous
#include <cuda_runtime.h>

#define NUM_NET 2
#define V 100000
#define D 128
#define B 4096
#define K 5
#define NS 10

#define NBLOCKS 2048   // 16384 warps / 8 warps-per-block
#define NTHREADS 256

__device__ float g_part[NBLOCKS];

__device__ __forceinline__ float logsig(float x) {
    // numerically stable log(sigmoid(x)) = min(x,0) - log1p(exp(-|x|))
    return fminf(x, 0.0f) - log1pf(expf(-fabsf(x)));
}

__device__ __forceinline__ float dot4(float4 a, float4 b) {
    return fmaf(a.x, b.x, fmaf(a.y, b.y, fmaf(a.z, b.z, a.w * b.w)));
}

// Sum of logsig(sign * (ctx_row . node_emb)) over M gathered rows,
// processed CH rows at a time with independent load/reduce chains.
template<int CH>
__device__ __forceinline__ float rows_sumN(const float* __restrict__ tab,
                                           const int* __restrict__ idx,
                                           int M, bool negate,
                                           float4 ne, int lane) {
    float a = 0.0f;
    for (int m = 0; m < M; m += CH) {
        float4 c[CH];
        #pragma unroll
        for (int u = 0; u < CH; u++) {
            int id = __ldg(idx + m + u);
            c[u] = __ldg(reinterpret_cast<const float4*>(tab + (size_t)id * D) + lane);
        }
        float s[CH];
        #pragma unroll
        for (int u = 0; u < CH; u++) s[u] = dot4(ne, c[u]);
        #pragma unroll
        for (int off = 16; off; off >>= 1) {
            #pragma unroll
            for (int u = 0; u < CH; u++)
                s[u] += __shfl_xor_sync(0xffffffffu, s[u], off);
        }
        #pragma unroll
        for (int u = 0; u < CH; u++) a += logsig(negate ? -s[u] : s[u]);
    }
    return a;
}

__global__ void __launch_bounds__(NTHREADS)
loss_kernel(const float* __restrict__ node_tables,
            const float* __restrict__ neigh_tables,
            const int* __restrict__ nodes_idx,
            const int* __restrict__ neigh_idx,
            const int* __restrict__ role_idx,
            const int* __restrict__ neg_main,
            const int* __restrict__ neg_node,
            const int* __restrict__ neg_cross,
            const int* __restrict__ neg_role) {
    const int lane = threadIdx.x & 31;
    const int wid  = threadIdx.x >> 5;
    const int gw   = blockIdx.x * (NTHREADS >> 5) + wid;   // 0 .. 16383

    const int pair = gw >> 1;          // (i, b) id, 0 .. 8191
    const int half = gw & 1;
    const int i = pair / B;
    const int b = pair % B;
    const int j = 1 - i;
    const size_t VD = (size_t)V * D;

    const float* nt_i = node_tables  + (size_t)i * VD;
    const float* nt_j = node_tables  + (size_t)j * VD;
    const float* gt_i = neigh_tables + (size_t)i * VD;
    const float* gt_j = neigh_tables + (size_t)j * VD;

    // node embedding for (i, b): 4 floats per lane
    const int nid = __ldg(nodes_idx + i * B + b);
    const float4 ne = __ldg(reinterpret_cast<const float4*>(nt_i + (size_t)nid * D) + lane);

    // total = -(1/10) * sum_t w_t * [ pos_mean + neg_sum_mean ]
    const float CB = 1.0f / (10.0f * (float)B);
    const float WH = 0.1f;

    float acc = 0.0f;
    if (half == 0) {
        // term 1: main SGNS on view i  (5 pos + 50 neg)
        acc += rows_sumN<5>(gt_i, neigh_idx + (i * B + b) * K, K, false, ne, lane) * (-CB / (float)K);
        acc += rows_sumN<5>(gt_i, neg_main + (size_t)(i * B + b) * (K * NS), K * NS, true, ne, lane) * (-CB);
        // term 2: cross-view node alignment  (1 pos + 10 neg)
        acc += rows_sumN<1>(nt_j, nodes_idx + i * B + b, 1, false, ne, lane) * (-WH * CB);
        acc += rows_sumN<5>(nt_j, neg_node + (size_t)((i * NUM_NET + j) * B + b) * NS, NS, true, ne, lane) * (-WH * CB);
    } else {
        // term 3: cross-view neighbor loss  (5 pos + 50 neg)
        acc += rows_sumN<5>(gt_j, neigh_idx + (i * B + b) * K, K, false, ne, lane) * (-WH * CB / (float)K);
        acc += rows_sumN<5>(gt_j, neg_cross + (size_t)((i * NUM_NET + j) * B + b) * (K * NS), K * NS, true, ne, lane) * (-WH * CB);
        // terms 4,5: role-based losses, j2 in {0,1}  (2 × (1 pos + 10 neg))
        #pragma unroll
        for (int j2 = 0; j2 < NUM_NET; j2++) {
            const float* nt = node_tables + (size_t)j2 * VD;
            acc += rows_sumN<1>(nt, role_idx + (i * NUM_NET + j2) * B + b, 1, false, ne, lane) * (-WH * CB);
            acc += rows_sumN<5>(nt, neg_role + (size_t)((i * NUM_NET + j2) * B + b) * NS, NS, true, ne, lane) * (-WH * CB);
        }
    }

    __shared__ float sacc[NTHREADS >> 5];
    if (lane == 0) sacc[wid] = acc;
    __syncthreads();
    if (threadIdx.x == 0) {
        float t = 0.0f;
        #pragma unroll
        for (int w = 0; w < (NTHREADS >> 5); w++) t += sacc[w];
        g_part[blockIdx.x] = t;   // always written: no zero-init kernel needed
    }
}

__global__ void __launch_bounds__(1024)
finalize_kernel(float* __restrict__ out) {
    __shared__ double sh[32];
    double t = 0.0;
    for (int k = threadIdx.x; k < NBLOCKS; k += 1024)
        t += (double)g_part[k];
    #pragma unroll
    for (int off = 16; off; off >>= 1)
        t += __shfl_xor_sync(0xffffffffu, t, off);
    if ((threadIdx.x & 31) == 0) sh[threadIdx.x >> 5] = t;
    __syncthreads();
    if (threadIdx.x < 32) {
        double v = sh[threadIdx.x];
        #pragma unroll
        for (int off = 16; off; off >>= 1)
            v += __shfl_xor_sync(0xffffffffu, v, off);
        if (threadIdx.x == 0) out[0] = (float)v;
    }
}

extern "C" void kernel_launch(void* const* d_in, const int* in_sizes, int n_in,
                              void* d_out, int out_size) {
    const float* node_tables  = (const float*)d_in[0];
    const float* neigh_tables = (const float*)d_in[1];
    const int*   nodes_idx    = (const int*)d_in[2];
    const int*   neigh_idx    = (const int*)d_in[3];
    const int*   role_idx     = (const int*)d_in[4];
    const int*   neg_main     = (const int*)d_in[5];
    const int*   neg_node     = (const int*)d_in[6];
    const int*   neg_cross    = (const int*)d_in[7];
    const int*   neg_role     = (const int*)d_in[8];

    (void)in_sizes; (void)n_in; (void)out_size;

    loss_kernel<<<NBLOCKS, NTHREADS>>>(node_tables, neigh_tables, nodes_idx,
                                       neigh_idx, role_idx, neg_main,
                                       neg_node, neg_cross, neg_role);
    finalize_kernel<<<1, 1024>>>((float*)d_out);
}